// round 3
// baseline (speedup 1.0000x reference)
#include <cuda_runtime.h>

#define NCLS  19
#define DIM   256
#define NPIX  4096
#define NBINS 51
#define NW    (NCLS * DIM)   // 4864 (c,d) tasks

// ---- scratch (no allocations allowed) ----
__device__ int   g_perm[NPIX];
__device__ int   g_off[NCLS + 1];
__device__ int   g_cnt[NCLS];
__device__ float g_Fs[DIM * NPIX];          // class-sorted, d-major
__device__ float g_clsum2[NCLS * 32];       // spread class partial sums

__device__ __forceinline__ float wredsum(float v) {
#pragma unroll
    for (int m = 16; m; m >>= 1) v += __shfl_xor_sync(0xffffffffu, v, m);
    return v;
}

__device__ __forceinline__ float ex2(float x) {
    float e;
    asm("ex2.approx.ftz.f32 %0, %1;" : "=f"(e) : "f"(x));
    return e;
}

// K0: dtype-sniff label (int64 vs int32), atomic-free counting sort by class.
// Rank construction: per-warp match_any + popc gives within-warp rank; per-warp
// per-class counters in smem (warp-private, no atomics) give within-warp
// running base; a tiny cross-warp scan gives warp bases; a serial 19-class
// scan gives class offsets.
__global__ void __launch_bounds__(1024) k_prep(const int* __restrict__ lab32) {
    __shared__ int scnt[32][20];   // [warp][class] counts -> prefix in-place
    __shared__ int soff[NCLS + 1];
    int tid  = threadIdx.x;
    int w    = tid >> 5;
    int lane = tid & 31;

    // dtype sniff: int64 labels (0..18) have all odd int32 words zero.
    int any = 0;
    for (int i = 2 * tid + 1; i < NPIX; i += 2 * 1024) any |= lab32[i];
    int is32 = __syncthreads_or(any);

    if (lane < 20) scnt[w][lane] = 0;
    if (tid < NCLS * 32) g_clsum2[tid] = 0.f;
    __syncwarp();

    int cs[4], rs[4];
#pragma unroll
    for (int it = 0; it < 4; it++) {
        int n = w * 128 + it * 32 + lane;
        int c = is32 ? lab32[n] : lab32[2 * n];
        c = max(0, min(NCLS - 1, c));
        unsigned mask = __match_any_sync(0xffffffffu, c);
        int base = scnt[w][c];
        cs[it] = c;
        rs[it] = base + __popc(mask & ((1u << lane) - 1u));
        if (lane == (__ffs(mask) - 1)) scnt[w][c] = base + __popc(mask);
        __syncwarp();
    }
    __syncthreads();

    // cross-warp exclusive prefix per class; totals -> g_cnt
    if (tid < NCLS) {
        int run = 0;
#pragma unroll
        for (int w2 = 0; w2 < 32; w2++) {
            int t = scnt[w2][tid];
            scnt[w2][tid] = run;
            run += t;
        }
        g_cnt[tid] = run;
        soff[tid] = run;   // temp: totals
    }
    __syncthreads();
    if (tid == 0) {
        int off = 0;
        for (int c = 0; c < NCLS; c++) {
            int t = soff[c];
            soff[c] = off;
            g_off[c] = off;
            off += t;
        }
        soff[NCLS] = off;
        g_off[NCLS] = off;
    }
    __syncthreads();

#pragma unroll
    for (int it = 0; it < 4; it++) {
        int n = w * 128 + it * 32 + lane;
        int c = cs[it];
        g_perm[soff[c] + scnt[w][c] + rs[it]] = n;
    }
}

// K1: gather feature into class-sorted order, d-major. Coalesced writes;
// gathers stay inside one 16KB row (L1/L2-resident).
__global__ void k_gather(const float* __restrict__ feature) {
    int d = blockIdx.x;
    const float* __restrict__ src = feature + d * NPIX;
    float* __restrict__ dst = g_Fs + d * NPIX;
    for (int j = threadIdx.x; j < NPIX; j += blockDim.x)
        dst[j] = src[g_perm[j]];
}

// K2 (heavy): one warp per (c,d). Fused stats + 51-bin KDE + full epilogue
// (normalize, gaussian target, smooth-L1) + spread atomic.
// Inner loop per (pixel,bin): 2 FFMA(imm) + EX2 + FADD -> MUFU-bound.
__global__ void __launch_bounds__(128) k_main() {
    __shared__ float sh[4][52];
    int wslot = threadIdx.x >> 5;
    int w = blockIdx.x * 4 + wslot;
    if (w >= NW) return;
    int lane = threadIdx.x & 31;
    int c = w >> 8;        // 4864 = 19*256
    int d = w & 255;
    int off = g_off[c];
    int cnt = g_off[c + 1] - off;
    if (cnt == 0) return;

    const float* __restrict__ fp = g_Fs + d * NPIX + off;

    // pass 1: per-class mean/var for this feature dim
    float s1 = 0.f, s2 = 0.f;
    for (int i = lane; i < cnt; i += 32) {
        float f = fp[i];
        s1 += f;
        s2 = fmaf(f, f, s2);
    }
    s1 = wredsum(s1);
    s2 = wredsum(s2);
    float cm  = (float)cnt;
    float miu = s1 / cm;
    float var = fmaxf(s2 / cm - miu * miu, 1e-12f);

    const float LOG2E = 1.4426950408889634f;
    // vs = var/25 ; base-2 exponent coef: -0.5/vs*log2e = -12.5*log2e/var
    float a_s = -12.5f * LOG2E / var;

    float acc[NBINS];
#pragma unroll
    for (int k = 0; k < NBINS; k++) acc[k] = 0.f;

    // pass 2: KDE accumulation. arg = a_s*bk^2 + p1*bk + p0 (bk, bk^2 imm).
    for (int i = lane; i < cnt; i += 32) {
        float f  = fp[i];
        float p1 = (-2.f * a_s) * f;
        float p0 = a_s * f * f;
#pragma unroll
        for (int k = 0; k < NBINS; k++) {
            float bk  = -5.f + 0.2f * (float)k;
            float arg = fmaf(a_s, bk * bk, fmaf(p1, bk, p0));
            acc[k] += ex2(arg);
        }
    }

#pragma unroll
    for (int k = 0; k < NBINS; k++) acc[k] = wredsum(acc[k]);

    // stash totals in smem so the epilogue can go lane-parallel
    if (lane == 0) {
#pragma unroll
        for (int k = 0; k < NBINS; k++) sh[wslot][k] = acc[k];
    }
    __syncwarp();

    // epilogue: lane k owns bins k and k+32
    bool hi = lane < (NBINS - 32);
    float sv0 = sh[wslot][lane];
    float sv1 = hi ? sh[wslot][lane + 32] : 0.f;
    float sumS = wredsum(sv0 + sv1);

    float at = -0.5f * LOG2E / var;
    float b0 = fmaf(0.2f, (float)lane, -5.f);
    float b1 = b0 + 6.4f;
    float d0 = b0 - miu, d1 = b1 - miu;
    float g0 = ex2(at * d0 * d0);
    float g1 = hi ? ex2(at * d1 * d1) : 0.f;
    float sumT = wredsum(g0 + g1);

    float invS = 1.f / fmaxf(sumS, 1e-30f);
    float invT = 1.f / fmaxf(sumT, 1e-30f);

    float df0 = sv0 * invS - g0 * invT;
    float df1 = sv1 * invS - g1 * invT;
    float ad0 = fabsf(df0), ad1 = fabsf(df1);
    float l0 = (ad0 < 1.f) ? 0.5f * df0 * df0 : ad0 - 0.5f;
    float l1 = (ad1 < 1.f) ? 0.5f * df1 * df1 : ad1 - 0.5f;
    if (!hi) l1 = 0.f;

    float sl = wredsum(l0 + l1);
    if (lane == 0) atomicAdd(&g_clsum2[c * 32 + (d & 31)], sl);
}

// K3: reduce spread sums, masked mean -> loss scalar.
__global__ void k_final(float* __restrict__ out) {
    int lane = threadIdx.x;
    float v = 0.f;
    for (int i = lane; i < NCLS * 32; i += 32) {
        int c = i >> 5;
        if (c > 0 && g_cnt[c] > 0) v += g_clsum2[i];
    }
    v = wredsum(v);
    float a = (lane >= 1 && lane < NCLS && g_cnt[lane] > 0) ? 1.f : 0.f;
    a = wredsum(a);
    if (lane == 0) out[0] = (v * (1.f / 13056.f)) / (a + 1e-12f);
}

extern "C" void kernel_launch(void* const* d_in, const int* in_sizes, int n_in,
                              void* d_out, int out_size) {
    // Inputs: feature (1048576 f32) and label (4096 px); smaller buffer = label.
    int fi = 0, li = 1;
    if (n_in >= 2 && in_sizes[0] < in_sizes[1]) { fi = 1; li = 0; }
    const float* feature = (const float*)d_in[fi];
    const int*   label   = (const int*)d_in[li];
    float* out = (float*)d_out;

    // Output layout: [loss, feature...] — copy first (independent work).
    if (out_size > 1) {
        size_t nf = (size_t)(out_size - 1);
        size_t cap = (size_t)DIM * NPIX;
        if (nf > cap) nf = cap;
        cudaMemcpyAsync(out + 1, feature, nf * sizeof(float),
                        cudaMemcpyDeviceToDevice);
    }

    k_prep<<<1, 1024>>>(label);
    k_gather<<<DIM, 256>>>(feature);
    k_main<<<(NW + 3) / 4, 128>>>();
    k_final<<<1, 32>>>(out);
}

// round 4
// speedup vs baseline: 1.1681x; 1.1681x over previous
#include <cuda_runtime.h>

#define NCLS  19
#define DIM   256
#define NPIX  4096
#define NBINS 51
#define NW    (NCLS * DIM)   // 4864 (c,d) tasks; grid 1216 x 4 warps exactly

// ---- scratch (no allocations allowed) ----
__device__ int   g_perm[NPIX];
__device__ int   g_off[NCLS + 1];
__device__ int   g_cnt[NCLS];
__device__ float g_Fs[DIM * NPIX];          // class-sorted, d-major
__device__ float g_clsum2[NCLS * 32];       // spread class partial sums
__device__ int   g_ticket;

__device__ __forceinline__ float wredsum(float v) {
#pragma unroll
    for (int m = 16; m; m >>= 1) v += __shfl_xor_sync(0xffffffffu, v, m);
    return v;
}

__device__ __forceinline__ float ex2(float x) {
    float e;
    asm("ex2.approx.ftz.f32 %0, %1;" : "=f"(e) : "f"(x));
    return e;
}

// K0: dtype-sniff label (int64 vs int32), atomic-free counting sort by class.
__global__ void __launch_bounds__(1024) k_prep(const int* __restrict__ lab32) {
    __shared__ int scnt[32][20];   // [warp][class] counts -> prefix in-place
    __shared__ int soff[NCLS + 1];
    int tid  = threadIdx.x;
    int w    = tid >> 5;
    int lane = tid & 31;

    // dtype sniff: int64 labels (0..18) have all odd int32 words zero.
    int any = 0;
    for (int i = 2 * tid + 1; i < NPIX; i += 2 * 1024) any |= lab32[i];
    int is32 = __syncthreads_or(any);

    if (lane < 20) scnt[w][lane] = 0;
    if (tid < NCLS * 32) g_clsum2[tid] = 0.f;
    if (tid == 0) g_ticket = 0;
    __syncwarp();

    int cs[4], rs[4];
#pragma unroll
    for (int it = 0; it < 4; it++) {
        int n = w * 128 + it * 32 + lane;
        int c = is32 ? lab32[n] : lab32[2 * n];
        c = max(0, min(NCLS - 1, c));
        unsigned mask = __match_any_sync(0xffffffffu, c);
        int base = scnt[w][c];
        cs[it] = c;
        rs[it] = base + __popc(mask & ((1u << lane) - 1u));
        if (lane == (__ffs(mask) - 1)) scnt[w][c] = base + __popc(mask);
        __syncwarp();
    }
    __syncthreads();

    // cross-warp exclusive prefix per class; totals -> g_cnt
    if (tid < NCLS) {
        int run = 0;
#pragma unroll
        for (int w2 = 0; w2 < 32; w2++) {
            int t = scnt[w2][tid];
            scnt[w2][tid] = run;
            run += t;
        }
        g_cnt[tid] = run;
        soff[tid] = run;   // temp: totals
    }
    __syncthreads();
    if (tid == 0) {
        int off = 0;
        for (int c = 0; c < NCLS; c++) {
            int t = soff[c];
            soff[c] = off;
            g_off[c] = off;
            off += t;
        }
        soff[NCLS] = off;
        g_off[NCLS] = off;
    }
    __syncthreads();

#pragma unroll
    for (int it = 0; it < 4; it++) {
        int n = w * 128 + it * 32 + lane;
        int c = cs[it];
        g_perm[soff[c] + scnt[w][c] + rs[it]] = n;
    }
}

// K1: gather feature into class-sorted order, d-major. Coalesced writes;
// gathers stay inside one 16KB row (L1/L2-resident).
__global__ void k_gather(const float* __restrict__ feature) {
    int d = blockIdx.x;
    const float* __restrict__ src = feature + d * NPIX;
    float* __restrict__ dst = g_Fs + d * NPIX;
    for (int j = threadIdx.x; j < NPIX; j += blockDim.x)
        dst[j] = src[g_perm[j]];
}

// K2 (heavy): one warp per (c,d). Fused stats + 51-bin KDE + epilogue
// (normalize, gaussian target, smooth-L1) + spread atomic + last-warp-ticket
// final reduction writing the loss scalar. No separate finalize kernel.
__global__ void __launch_bounds__(128) k_main(float* __restrict__ out) {
    __shared__ float sh[4][52];
    int wslot = threadIdx.x >> 5;
    int w = blockIdx.x * 4 + wslot;
    int lane = threadIdx.x & 31;
    int c = w >> 8;        // 4864 = 19*256
    int d = w & 255;
    int off = g_off[c];
    int cnt = g_off[c + 1] - off;

    const float LOG2E = 1.4426950408889634f;

    if (cnt > 0) {
        const float* __restrict__ fp = g_Fs + d * NPIX + off;

        // pass 1: per-class mean/var for this feature dim
        float s1 = 0.f, s2 = 0.f;
        for (int i = lane; i < cnt; i += 32) {
            float f = fp[i];
            s1 += f;
            s2 = fmaf(f, f, s2);
        }
        s1 = wredsum(s1);
        s2 = wredsum(s2);
        float cm  = (float)cnt;
        float miu = s1 / cm;
        float var = fmaxf(s2 / cm - miu * miu, 1e-12f);

        // vs = var/25 ; base-2 exponent coef: -0.5/vs*log2e = -12.5*log2e/var
        float a_s = -12.5f * LOG2E / var;

        float acc[NBINS];
#pragma unroll
        for (int k = 0; k < NBINS; k++) acc[k] = 0.f;

        // pass 2: KDE. arg = a_s*bk^2 + p1*bk + p0 (bk, bk^2 imm).
        for (int i = lane; i < cnt; i += 32) {
            float f  = fp[i];
            float p1 = (-2.f * a_s) * f;
            float p0 = a_s * f * f;
#pragma unroll
            for (int k = 0; k < NBINS; k++) {
                float bk  = -5.f + 0.2f * (float)k;
                float arg = fmaf(a_s, bk * bk, fmaf(p1, bk, p0));
                acc[k] += ex2(arg);
            }
        }

#pragma unroll
        for (int k = 0; k < NBINS; k++) acc[k] = wredsum(acc[k]);

        // stash totals so the epilogue can go lane-parallel
        if (lane == 0) {
#pragma unroll
            for (int k = 0; k < NBINS; k++) sh[wslot][k] = acc[k];
        }
        __syncwarp();

        // epilogue: lane k owns bins k and k+32
        bool hi = lane < (NBINS - 32);
        float sv0 = sh[wslot][lane];
        float sv1 = hi ? sh[wslot][lane + 32] : 0.f;
        float sumS = wredsum(sv0 + sv1);

        float at = -0.5f * LOG2E / var;
        float b0 = fmaf(0.2f, (float)lane, -5.f);
        float b1 = b0 + 6.4f;
        float d0 = b0 - miu, d1 = b1 - miu;
        float g0 = ex2(at * d0 * d0);
        float g1 = hi ? ex2(at * d1 * d1) : 0.f;
        float sumT = wredsum(g0 + g1);

        float invS = 1.f / fmaxf(sumS, 1e-30f);
        float invT = 1.f / fmaxf(sumT, 1e-30f);

        float df0 = sv0 * invS - g0 * invT;
        float df1 = sv1 * invS - g1 * invT;
        float ad0 = fabsf(df0), ad1 = fabsf(df1);
        float l0 = (ad0 < 1.f) ? 0.5f * df0 * df0 : ad0 - 0.5f;
        float l1 = (ad1 < 1.f) ? 0.5f * df1 * df1 : ad1 - 0.5f;
        if (!hi) l1 = 0.f;

        float sl = wredsum(l0 + l1);
        if (lane == 0) atomicAdd(&g_clsum2[c * 32 + (d & 31)], sl);
    }

    // publish, then take a ticket; the last of the NW warps finalizes.
    __threadfence();
    int tk = 0;
    if (lane == 0) tk = atomicAdd(&g_ticket, 1);
    tk = __shfl_sync(0xffffffffu, tk, 0);
    if (tk == NW - 1) {
        float v = 0.f, a = 0.f;
#pragma unroll
        for (int j = 1; j < NCLS; j++) {          // class 0 excluded
            int cj = __ldcg(&g_cnt[j]);
            float x = __ldcg(&g_clsum2[j * 32 + lane]);
            if (cj > 0) { v += x; a += (lane == 0) ? 1.f : 0.f; }
        }
        v = wredsum(v);
        a = wredsum(a);
        if (lane == 0) out[0] = (v * (1.f / 13056.f)) / (a + 1e-12f);
    }
}

extern "C" void kernel_launch(void* const* d_in, const int* in_sizes, int n_in,
                              void* d_out, int out_size) {
    // Inputs: feature (1048576 f32) and label (4096 px); smaller buffer = label.
    int fi = 0, li = 1;
    if (n_in >= 2 && in_sizes[0] < in_sizes[1]) { fi = 1; li = 0; }
    const float* feature = (const float*)d_in[fi];
    const int*   label   = (const int*)d_in[li];
    float* out = (float*)d_out;

    // Output layout: [loss, feature...] — copy first (independent work).
    if (out_size > 1) {
        size_t nf = (size_t)(out_size - 1);
        size_t cap = (size_t)DIM * NPIX;
        if (nf > cap) nf = cap;
        cudaMemcpyAsync(out + 1, feature, nf * sizeof(float),
                        cudaMemcpyDeviceToDevice);
    }

    k_prep<<<1, 1024>>>(label);
    k_gather<<<DIM, 256>>>(feature);
    k_main<<<NW / 4, 128>>>(out);
}